// round 13
// baseline (speedup 1.0000x reference)
#include <cuda_runtime.h>
#include <cstdint>

constexpr int IMG_N  = 256;
constexpr int NDET   = 368;
constexpr int NVIEW  = 180;
constexpr int NSAMP  = 513;
constexpr int NRAY   = NDET * NVIEW;  // 66240
constexpr int RAYS_PER_BLOCK = 8;     // one warp per ray

// Padded quad images: quad[v][u] = (P(v,u), P(v,u+1), P(v+1,u), P(v+1,u+1))
// where P is the zero-padded image (2-pixel border).
constexpr int PB = 2;
constexpr int PW = 264;
constexpr int PH = 260;

__device__ float4 g_quadP [PH * PW];   // normal orientation
__device__ float4 g_quadTP[PH * PW];   // transposed orientation

__global__ void prep_kernel(const float* __restrict__ img)
{
    const int idx = blockIdx.x * 256 + threadIdx.x;
    if (idx >= PH * PW) return;
    const int r = idx / PW, c = idx % PW;

    auto P = [&](int rr, int cc) -> float {
        const int y = rr - PB, x = cc - PB;
        return ((x >= 0) & (x < IMG_N) & (y >= 0) & (y < IMG_N))
               ? img[y * IMG_N + x] : 0.0f;
    };
    auto PT = [&](int rr, int cc) -> float {
        const int y = rr - PB, x = cc - PB;
        return ((x >= 0) & (x < IMG_N) & (y >= 0) & (y < IMG_N))
               ? img[x * IMG_N + y] : 0.0f;
    };

    g_quadP [idx] = make_float4(P (r, c), P (r, c + 1), P (r + 1, c), P (r + 1, c + 1));
    g_quadTP[idx] = make_float4(PT(r, c), PT(r, c + 1), PT(r + 1, c), PT(r + 1, c + 1));
}

// Bilinear sample: ONE float4 gather fetches all four corners.
// Valid samples have iu,iv in [-1.0, 256.01]; clamp [-1.5, 256.5] is a no-op
// for them and keeps zero-weight garbage coords in-bounds:
// floor in [-2, 256], +PB <= 258 < PH-1, PW-1.
__device__ __forceinline__ float bilinQ(const float4* __restrict__ qim,
                                        float u, float v, float wgt)
{
    float iu = fmaf(u, 128.0f, 127.5f);
    float iv = fmaf(v, 128.0f, 127.5f);
    iu = fminf(fmaxf(iu, -1.5f), 256.5f);
    iv = fminf(fmaxf(iv, -1.5f), 256.5f);
    const float fu = floorf(iu);
    const float fv = floorf(iv);
    const int u0 = (int)fu, v0 = (int)fv;
    const float wu1 = iu - fu, wv1 = iv - fv;
    const float wu0 = 1.0f - wu1, wv0 = 1.0f - wv1;

    const float4 q = __ldg(&qim[(v0 + PB) * PW + (u0 + PB)]);

    const float top = fmaf(wu1, q.y, wu0 * q.x);
    const float bot = fmaf(wu1, q.w, wu0 * q.z);
    return wgt * fmaf(wv1, bot, wv0 * top);
}

template<bool TR>
__device__ __forceinline__ float ray_accum(const float4* __restrict__ qim,
                                           const float2* __restrict__ g,
                                           const float* __restrict__ w,
                                           int lane)
{
    float acc = 0.0f;
    // 512 samples per warp: 4 chunks of 4 strided batches, s = lane + 32*k.
    // 4-wide batches keep live registers ~32 -> 7+ CTAs/SM while still
    // front-loading 12 independent loads per chunk.
    #pragma unroll
    for (int c = 0; c < 4; c++) {
        float2 p[4];
        float  pw[4];
        #pragma unroll
        for (int j = 0; j < 4; j++) {
            const int s = lane + 32 * (c * 4 + j);
            p[j]  = __ldcs(&g[s]);
            pw[j] = __ldcs(&w[s]);
        }
        #pragma unroll
        for (int j = 0; j < 4; j++) {
            const float u = TR ? p[j].y : p[j].x;
            const float v = TR ? p[j].x : p[j].y;
            acc += bilinQ(qim, u, v, pw[j]);
        }
    }
    // Odd tail sample s = 512 (lane 0 only).
    if (lane == 0) {
        const float2 p = __ldg(&g[512]);
        const float  wv = __ldg(&w[512]);
        acc += bilinQ(qim, TR ? p.y : p.x, TR ? p.x : p.y, wv);
    }
    return acc;
}

__global__ __launch_bounds__(256, 7)
void fp_kernel(const float2* __restrict__ grid,   // [NRAY, NSAMP] (gx, gy)
               const float* __restrict__ wt,      // [NRAY, NSAMP]
               float* __restrict__ out)           // [NRAY]
{
    const int wid  = threadIdx.x >> 5;
    const int lane = threadIdx.x & 31;
    const int ray  = blockIdx.x * RAYS_PER_BLOCK + wid;

    const float2* __restrict__ g = grid + (size_t)ray * NSAMP;
    const float*  __restrict__ w = wt   + (size_t)ray * NSAMP;

    // Per-ray orientation: make the fast-moving coordinate contiguous.
    const float2 ga = __ldg(&g[0]);
    const float2 gb = __ldg(&g[NSAMP - 1]);
    const bool   tr = fabsf(gb.x - ga.x) < fabsf(gb.y - ga.y);

    float acc;
    if (tr) acc = ray_accum<true >(g_quadTP, g, w, lane);
    else    acc = ray_accum<false>(g_quadP,  g, w, lane);

    // Warp reduction — no smem, no barriers.
    #pragma unroll
    for (int o = 16; o > 0; o >>= 1)
        acc += __shfl_down_sync(0xFFFFFFFFu, acc, o);

    if (lane == 0) out[ray] = acc;
}

extern "C" void kernel_launch(void* const* d_in, const int* in_sizes, int n_in,
                              void* d_out, int out_size)
{
    const float*  img  = (const float*)d_in[0];   // [1,1,256,256]
    const float2* grid = (const float2*)d_in[1];  // [368,180,513,2]
    const float*  wt   = (const float*)d_in[2];   // [1,1,368,180,513]
    float* out = (float*)d_out;                   // [1,1,368,180]
    (void)in_sizes; (void)n_in; (void)out_size;

    prep_kernel<<<(PH * PW + 255) / 256, 256>>>(img);
    fp_kernel<<<NRAY / RAYS_PER_BLOCK, 256>>>(grid, wt, out);
}